// round 14
// baseline (speedup 1.0000x reference)
#include <cuda_runtime.h>
#include <cuda_fp16.h>
#include <cstdint>

#define NODES  100000
#define INDIM  512
#define H1DIM  256
#define H2DIM  128
#define ENDDIM 64
#define MAXE   3200000

// ---------------- scratch (device globals; referenced ONLY from device code) ----------------
__device__ __align__(128) __half g_XWh [(size_t)NODES * H1DIM];  // X@W1 (UNscaled), fp16
__device__ __align__(128) __half g_A2h [(size_t)NODES * H1DIM];  // relu(agg1*s_in+b1)*s_out, fp16
__device__ __align__(128) __half g_H2ph[(size_t)NODES * H2DIM];  // A2@W2, fp16
__device__ __align__(128) float  g_sout[NODES];
__device__ __align__(128) float  g_sin [NODES];
__device__ __align__(16)  int    g_cnt_in [NODES];
__device__ __align__(16)  int    g_cnt_out[NODES];
__device__ __align__(16)  int    g_cursor [NODES];
__device__ __align__(16)  int    g_rowstart[NODES + 1];
__device__ __align__(16)  int    g_esrc[MAXE];
__device__ __align__(16)  int    g_blocksum[128];

// ---------------- zero count arrays ----------------
__global__ void zero_kernel(int M) {
    int i = blockIdx.x * blockDim.x + threadIdx.x;
    if (i < M) { g_cnt_in[i] = 0; g_cnt_out[i] = 0; }
}

// ---------------- scan phase 1 (+ degree->scale finalize folded in) ----------------
__global__ void scan1_kernel(int M) {
    __shared__ int s[1024];
    int tid = threadIdx.x;
    int i = blockIdx.x * 1024 + tid;
    int v = (i < M) ? g_cnt_in[i] : 0;
    if (i < M) {
        g_sout[i] = rsqrtf((float)max(g_cnt_out[i], 1));
        g_sin [i] = rsqrtf((float)max(v, 1));
    }
    s[tid] = v;
    __syncthreads();
    #pragma unroll
    for (int off = 1; off < 1024; off <<= 1) {
        int t = (tid >= off) ? s[tid - off] : 0;
        __syncthreads();
        s[tid] += t;
        __syncthreads();
    }
    if (i < M) g_rowstart[i] = s[tid] - v;
    if (tid == 1023) g_blocksum[blockIdx.x] = s[1023];
}

__global__ void scan2_kernel(int nb) {
    __shared__ int s[128];
    int tid = threadIdx.x;
    int v = (tid < nb) ? g_blocksum[tid] : 0;
    s[tid] = v;
    __syncthreads();
    #pragma unroll
    for (int off = 1; off < 128; off <<= 1) {
        int t = (tid >= off) ? s[tid - off] : 0;
        __syncthreads();
        s[tid] += t;
        __syncthreads();
    }
    if (tid < nb) g_blocksum[tid] = s[tid] - v;
}

// Phase 3: add block offsets; seed cursor with rowstart; sentinel.
__global__ void scan3_kernel(int M, int E) {
    int i = blockIdx.x * blockDim.x + threadIdx.x;
    if (i < M) {
        int v = g_rowstart[i] + g_blocksum[i >> 10];
        g_rowstart[i] = v;
        g_cursor[i] = v;
    }
    if (i == 0) g_rowstart[M] = E;
}

// ---------------- tf32 helpers ----------------
__device__ __forceinline__ uint32_t f2tf32(float f) {
    uint32_t r;
    asm("cvt.rna.tf32.f32 %0, %1;" : "=r"(r) : "f"(f));
    return r;
}

__device__ __forceinline__ void mma_tf32(float* c, const uint32_t* a, const uint32_t* b) {
    asm volatile(
        "mma.sync.aligned.m16n8k8.row.col.f32.tf32.tf32.f32 "
        "{%0,%1,%2,%3}, {%4,%5,%6,%7}, {%8,%9}, {%0,%1,%2,%3};\n"
        : "+f"(c[0]), "+f"(c[1]), "+f"(c[2]), "+f"(c[3])
        : "r"(a[0]), "r"(a[1]), "r"(a[2]), "r"(a[3]), "r"(b[0]), "r"(b[1]));
}

// ---------------- tf32 GEMM body (device function; caller provides block coords) ----------------
// LAYER==1: g_XWh  = features @ W1 (UNscaled)   [A fp32, K=512, N=256]
// LAYER==2: g_H2ph = g_A2h @ W2                 [A fp16, K=256, N=128]
// BM=128, BN=128, BK=16; 8 warps 2(M)x4(N); warp tile 64x32 of m16n8k8 mmas.
template <int LAYER>
__device__ __forceinline__ void gemm_body(const float* __restrict__ A_ext,
                                          const float* __restrict__ B, int M,
                                          int bx, int by)
{
    const int K = (LAYER == 1) ? INDIM : H1DIM;
    const int N = (LAYER == 1) ? H1DIM : H2DIM;
    __half* C = (LAYER == 1) ? g_XWh : g_H2ph;

    const int BM = 128, BK = 16;
    const int AS = 136;
    __shared__ uint32_t As[2][BK * AS];
    __shared__ uint32_t Bs[2][BK * AS];

    int tid = threadIdx.x;
    int lane = tid & 31;
    int w = tid >> 5;
    int wm = w & 1;
    int wn = w >> 1;
    int g = lane >> 2, t4 = lane & 3;

    int row0 = by * BM;
    int col0 = bx * 128;

    int ar = tid >> 1, ac = (tid & 1) * 8;
    int arow = row0 + ar;
    bool rowok = (arow < M);

    int br = tid >> 4, bc = (tid & 15) * 8;

    float acc[4][4][4];
    #pragma unroll
    for (int mt = 0; mt < 4; mt++)
        #pragma unroll
        for (int nt = 0; nt < 4; nt++)
            #pragma unroll
            for (int i = 0; i < 4; i++) acc[mt][nt][i] = 0.f;

    float av[8];
    float4 b0v, b1v;

    auto load_regs = [&](int k0) {
        if (rowok) {
            if (LAYER == 1) {
                const float4* ap = reinterpret_cast<const float4*>(A_ext + (size_t)arow * K + k0 + ac);
                float4 a0 = ap[0], a1 = ap[1];
                av[0]=a0.x; av[1]=a0.y; av[2]=a0.z; av[3]=a0.w;
                av[4]=a1.x; av[5]=a1.y; av[6]=a1.z; av[7]=a1.w;
            } else {
                uint4 ah = *reinterpret_cast<const uint4*>(g_A2h + (size_t)arow * K + k0 + ac);
                float2 p0 = __half22float2(*reinterpret_cast<__half2*>(&ah.x));
                float2 p1 = __half22float2(*reinterpret_cast<__half2*>(&ah.y));
                float2 p2 = __half22float2(*reinterpret_cast<__half2*>(&ah.z));
                float2 p3 = __half22float2(*reinterpret_cast<__half2*>(&ah.w));
                av[0]=p0.x; av[1]=p0.y; av[2]=p1.x; av[3]=p1.y;
                av[4]=p2.x; av[5]=p2.y; av[6]=p3.x; av[7]=p3.y;
            }
        } else {
            #pragma unroll
            for (int i = 0; i < 8; i++) av[i] = 0.f;
        }
        const float4* bp = reinterpret_cast<const float4*>(B + (size_t)(k0 + br) * N + col0 + bc);
        b0v = bp[0]; b1v = bp[1];
    };

    auto store_smem = [&](int b) {
        #pragma unroll
        for (int i = 0; i < 8; i++)
            As[b][(ac + i) * AS + ar] = f2tf32(av[i]);
        Bs[b][br * AS + bc + 0] = f2tf32(b0v.x);
        Bs[b][br * AS + bc + 1] = f2tf32(b0v.y);
        Bs[b][br * AS + bc + 2] = f2tf32(b0v.z);
        Bs[b][br * AS + bc + 3] = f2tf32(b0v.w);
        Bs[b][br * AS + bc + 4] = f2tf32(b1v.x);
        Bs[b][br * AS + bc + 5] = f2tf32(b1v.y);
        Bs[b][br * AS + bc + 6] = f2tf32(b1v.z);
        Bs[b][br * AS + bc + 7] = f2tf32(b1v.w);
    };

    load_regs(0);
    store_smem(0);
    __syncthreads();

    int buf = 0;
    for (int k0 = 0; k0 < K; k0 += BK) {
        bool more = (k0 + BK < K);
        if (more) load_regs(k0 + BK);

        #pragma unroll
        for (int kk = 0; kk < BK; kk += 8) {
            uint32_t af[4][4], bf[4][2];
            #pragma unroll
            for (int mt = 0; mt < 4; mt++) {
                int m = wm * 64 + mt * 16 + g;
                af[mt][0] = As[buf][(kk + t4) * AS + m];
                af[mt][1] = As[buf][(kk + t4) * AS + m + 8];
                af[mt][2] = As[buf][(kk + t4 + 4) * AS + m];
                af[mt][3] = As[buf][(kk + t4 + 4) * AS + m + 8];
            }
            #pragma unroll
            for (int nt = 0; nt < 4; nt++) {
                int n = wn * 32 + nt * 8 + g;
                bf[nt][0] = Bs[buf][(kk + t4) * AS + n];
                bf[nt][1] = Bs[buf][(kk + t4 + 4) * AS + n];
            }
            #pragma unroll
            for (int mt = 0; mt < 4; mt++)
                #pragma unroll
                for (int nt = 0; nt < 4; nt++)
                    mma_tf32(acc[mt][nt], af[mt], bf[nt]);
        }

        if (more) store_smem(buf ^ 1);
        __syncthreads();
        buf ^= 1;
    }

    #pragma unroll
    for (int mt = 0; mt < 4; mt++) {
        int r = row0 + wm * 64 + mt * 16 + g;
        #pragma unroll
        for (int nt = 0; nt < 4; nt++) {
            int cb = col0 + wn * 32 + nt * 8 + t4 * 2;
            if (r < M) {
                __half2 v = __floats2half2_rn(acc[mt][nt][0], acc[mt][nt][1]);
                *reinterpret_cast<__half2*>(C + (size_t)r * N + cb) = v;
            }
            if (r + 8 < M) {
                __half2 v = __floats2half2_rn(acc[mt][nt][2], acc[mt][nt][3]);
                *reinterpret_cast<__half2*>(C + (size_t)(r + 8) * N + cb) = v;
            }
        }
    }
}

// ---------------- fused: degree count + GEMM1 rows [0, byHalf*128) ----------------
// even blocks: gemm tile; odd blocks: count grid-stride.
__global__ __launch_bounds__(256, 2)
void count_gemm1a_kernel(const float* __restrict__ features, const float* __restrict__ W1,
                         const int* __restrict__ src, const int* __restrict__ dst,
                         int M, int E)
{
    int G = gridDim.x >> 1;
    if ((blockIdx.x & 1) == 0) {
        int id = blockIdx.x >> 1;            // 0 .. 2*byHalf-1
        gemm_body<1>(features, W1, M, id & 1, id >> 1);
    } else {
        int fid = blockIdx.x >> 1;
        int i = fid * 256 + threadIdx.x;
        int stride = G * 256;
        for (; i < E; i += stride) {
            atomicAdd(&g_cnt_out[src[i]], 1);
            atomicAdd(&g_cnt_in [dst[i]], 1);
        }
    }
}

// ---------------- fused: CSR fill + GEMM1 rows [byHalf*128, M) ----------------
__global__ __launch_bounds__(256, 2)
void fill_gemm1b_kernel(const float* __restrict__ features, const float* __restrict__ W1,
                        const int* __restrict__ src, const int* __restrict__ dst,
                        int M, int E, int byHalf)
{
    int G = gridDim.x >> 1;
    if ((blockIdx.x & 1) == 0) {
        int id = blockIdx.x >> 1;
        gemm_body<1>(features, W1, M, id & 1, byHalf + (id >> 1));
    } else {
        int fid = blockIdx.x >> 1;
        int i = fid * 256 + threadIdx.x;
        int stride = G * 256;
        for (; i < E; i += stride) {
            int pos = atomicAdd(&g_cursor[dst[i]], 1);
            g_esrc[pos] = src[i];
        }
    }
}

// ---------------- GEMM2 ----------------
__global__ __launch_bounds__(256, 2)
void gemm2_kernel(const float* __restrict__ B, int M)
{
    gemm_body<2>(nullptr, B, M, blockIdx.x, blockIdx.y);
}

// ---------------- layer-1 aggregation: gather s_out[src]*XWu[src], + epilogue, fp16 out ----------------
// g_A2h[n,:] = relu( (sum_{e: dst==n} s_out[src_e]*XWu[src_e,:]) * s_in[n] + b1 ) * s_out[n]
__global__ __launch_bounds__(256)
void agg1_kernel(const float* __restrict__ b1, int M)
{
    int warp = (blockIdx.x * blockDim.x + threadIdx.x) >> 5;
    int lane = threadIdx.x & 31;
    int nw = (gridDim.x * blockDim.x) >> 5;
    float4 bb0 = *reinterpret_cast<const float4*>(b1 + lane * 8);
    float4 bb1 = *reinterpret_cast<const float4*>(b1 + lane * 8 + 4);

    for (int n = warp; n < M; n += nw) {
        int beg = g_rowstart[n], end = g_rowstart[n + 1];
        float a[8];
        #pragma unroll
        for (int i = 0; i < 8; i++) a[i] = 0.f;
        for (int e0 = beg; e0 < end; e0 += 32) {
            int mye = e0 + lane;
            int sv = 0; float scv = 0.f;
            if (mye < end) { sv = g_esrc[mye]; scv = g_sout[sv]; }
            int cnt = min(32, end - e0);
            for (int j = 0; j < cnt; j++) {
                int s = __shfl_sync(0xffffffff, sv, j);
                float sc = __shfl_sync(0xffffffff, scv, j);
                uint4 v = reinterpret_cast<const uint4*>(g_XWh + (size_t)s * H1DIM)[lane];
                float2 p0 = __half22float2(*reinterpret_cast<__half2*>(&v.x));
                float2 p1 = __half22float2(*reinterpret_cast<__half2*>(&v.y));
                float2 p2 = __half22float2(*reinterpret_cast<__half2*>(&v.z));
                float2 p3 = __half22float2(*reinterpret_cast<__half2*>(&v.w));
                a[0] = fmaf(p0.x, sc, a[0]); a[1] = fmaf(p0.y, sc, a[1]);
                a[2] = fmaf(p1.x, sc, a[2]); a[3] = fmaf(p1.y, sc, a[3]);
                a[4] = fmaf(p2.x, sc, a[4]); a[5] = fmaf(p2.y, sc, a[5]);
                a[6] = fmaf(p3.x, sc, a[6]); a[7] = fmaf(p3.y, sc, a[7]);
            }
        }
        float si = g_sin[n], so = g_sout[n];
        float o[8];
        o[0] = fmaxf(fmaf(a[0], si, bb0.x), 0.f) * so;
        o[1] = fmaxf(fmaf(a[1], si, bb0.y), 0.f) * so;
        o[2] = fmaxf(fmaf(a[2], si, bb0.z), 0.f) * so;
        o[3] = fmaxf(fmaf(a[3], si, bb0.w), 0.f) * so;
        o[4] = fmaxf(fmaf(a[4], si, bb1.x), 0.f) * so;
        o[5] = fmaxf(fmaf(a[5], si, bb1.y), 0.f) * so;
        o[6] = fmaxf(fmaf(a[6], si, bb1.z), 0.f) * so;
        o[7] = fmaxf(fmaf(a[7], si, bb1.w), 0.f) * so;
        uint4 pack;
        *reinterpret_cast<__half2*>(&pack.x) = __floats2half2_rn(o[0], o[1]);
        *reinterpret_cast<__half2*>(&pack.y) = __floats2half2_rn(o[2], o[3]);
        *reinterpret_cast<__half2*>(&pack.z) = __floats2half2_rn(o[4], o[5]);
        *reinterpret_cast<__half2*>(&pack.w) = __floats2half2_rn(o[6], o[7]);
        reinterpret_cast<uint4*>(g_A2h + (size_t)n * H1DIM)[lane] = pack;
    }
}

// ---------------- layer-2 aggregation (fp16 gather) + full MLP head ----------------
__global__ __launch_bounds__(256)
void agg2_head_kernel(const float* __restrict__ b2,
                      const float* __restrict__ Wo1, const float* __restrict__ bo1,
                      const float* __restrict__ Wo2, const float* __restrict__ bo2,
                      float* __restrict__ out, int M)
{
    __shared__ float sW1[H2DIM * ENDDIM];   // 32 KB
    __shared__ float sW2[ENDDIM];
    __shared__ float sb1[ENDDIM];
    __shared__ float h2[8][H2DIM];

    int tid = threadIdx.x;
    for (int i = tid; i < H2DIM * ENDDIM; i += blockDim.x) sW1[i] = Wo1[i];
    if (tid < ENDDIM) { sW2[tid] = Wo2[tid]; sb1[tid] = bo1[tid]; }
    __syncthreads();

    int warp = tid >> 5, lane = tid & 31;
    int gw = blockIdx.x * 8 + warp;
    int nw = gridDim.x * 8;
    float bo2v = bo2[0];
    float4 bb = reinterpret_cast<const float4*>(b2)[lane];

    for (int n = gw; n < M; n += nw) {
        int beg = g_rowstart[n], end = g_rowstart[n + 1];
        float a0 = 0.f, a1 = 0.f, a2 = 0.f, a3 = 0.f;
        for (int e0 = beg; e0 < end; e0 += 32) {
            int mye = e0 + lane;
            int sv = (mye < end) ? g_esrc[mye] : 0;
            int cnt = min(32, end - e0);
            for (int j = 0; j < cnt; j++) {
                int s = __shfl_sync(0xffffffff, sv, j);
                uint2 v = reinterpret_cast<const uint2*>(g_H2ph + (size_t)s * H2DIM)[lane];
                float2 p0 = __half22float2(*reinterpret_cast<__half2*>(&v.x));
                float2 p1 = __half22float2(*reinterpret_cast<__half2*>(&v.y));
                a0 += p0.x; a1 += p0.y; a2 += p1.x; a3 += p1.y;
            }
        }
        float si = g_sin[n];
        h2[warp][lane * 4 + 0] = fmaf(a0, si, bb.x);
        h2[warp][lane * 4 + 1] = fmaf(a1, si, bb.y);
        h2[warp][lane * 4 + 2] = fmaf(a2, si, bb.z);
        h2[warp][lane * 4 + 3] = fmaf(a3, si, bb.w);
        __syncwarp();

        float accs = 0.f;
        #pragma unroll
        for (int jj = 0; jj < 2; jj++) {
            int j = lane + jj * 32;
            float t = sb1[j];
            #pragma unroll 8
            for (int k = 0; k < H2DIM; k++)
                t = fmaf(h2[warp][k], sW1[k * ENDDIM + j], t);
            t = fmaxf(t, 0.f);
            accs = fmaf(t, sW2[j], accs);
        }
        #pragma unroll
        for (int o = 16; o > 0; o >>= 1)
            accs += __shfl_down_sync(0xffffffff, accs, o);
        if (lane == 0) out[n] = accs + bo2v;
        __syncwarp();
    }
}

// ---------------- launch ----------------
extern "C" void kernel_launch(void* const* d_in, const int* in_sizes, int n_in,
                              void* d_out, int out_size)
{
    const float* features = (const float*)d_in[0];
    const int*   src      = (const int*)  d_in[1];
    const int*   dst      = (const int*)  d_in[2];
    const float* W1       = (const float*)d_in[3];
    const float* b1       = (const float*)d_in[4];
    const float* W2       = (const float*)d_in[5];
    const float* b2       = (const float*)d_in[6];
    const float* Wo1      = (const float*)d_in[7];
    const float* bo1      = (const float*)d_in[8];
    const float* Wo2      = (const float*)d_in[9];
    const float* bo2      = (const float*)d_in[10];
    float* out = (float*)d_out;

    int M = in_sizes[0] / INDIM;   // 100000
    int E = in_sizes[1];           // 3200000

    zero_kernel<<<(M + 255) / 256, 256>>>(M);

    int nby = (M + 127) / 128;     // 782
    int byHalf = nby / 2;          // 391

    // K1: count (odd blocks) + gemm1 rows [0, byHalf*128) (even blocks)
    count_gemm1a_kernel<<<2 * (2 * byHalf), 256>>>(features, W1, src, dst, M, E);

    int nb = (M + 1023) / 1024;    // 98
    scan1_kernel<<<nb, 1024>>>(M);         // also computes s_out/s_in
    scan2_kernel<<<1, 128>>>(nb);
    scan3_kernel<<<(M + 255) / 256, 256>>>(M, E);

    // K2: fill (odd blocks) + gemm1 rows [byHalf*128, M) (even blocks)
    fill_gemm1b_kernel<<<2 * (2 * (nby - byHalf)), 256>>>(features, W1, src, dst, M, E, byHalf);

    agg1_kernel<<<(M * 32 + 255) / 256, 256>>>(b1, M);

    // Layer 2: g_H2ph = g_A2h @ W2   (M x 256 @ 256 x 128)
    gemm2_kernel<<<dim3(H2DIM / 128, (M + 127) / 128), 256>>>(W2, M);
    agg2_head_kernel<<<(M + 7) / 8, 256>>>(b2, Wo1, bo1, Wo2, bo2, out, M);
}

// round 15
// speedup vs baseline: 1.0174x; 1.0174x over previous
#include <cuda_runtime.h>
#include <cuda_fp16.h>
#include <cstdint>

#define NODES  100000
#define INDIM  512
#define H1DIM  256
#define H2DIM  128
#define ENDDIM 64
#define MAXE   3200000

// ---------------- scratch (device globals; referenced ONLY from device code) ----------------
__device__ __align__(128) __half g_XWh [(size_t)NODES * H1DIM];  // X@W1 (UNscaled), fp16
__device__ __align__(128) __half g_A2h [(size_t)NODES * H1DIM];  // relu(agg1*s_in+b1)*s_out, fp16
__device__ __align__(128) __half g_H2ph[(size_t)NODES * H2DIM];  // A2@W2, fp16
__device__ __align__(128) float  g_sout[NODES];
__device__ __align__(128) float  g_sin [NODES];
__device__ __align__(16)  int    g_cnt_in [NODES];
__device__ __align__(16)  int    g_cnt_out[NODES];
__device__ __align__(16)  int    g_cursor [NODES];
__device__ __align__(16)  int    g_rowstart[NODES + 1];
__device__ __align__(16)  int    g_esrc[MAXE];
__device__ __align__(16)  int    g_blocksum[128];

// ---------------- zero count arrays ----------------
__global__ void zero_kernel(int M) {
    int i = blockIdx.x * blockDim.x + threadIdx.x;
    if (i < M) { g_cnt_in[i] = 0; g_cnt_out[i] = 0; }
}

// ---------------- scan phase 1 (+ degree->scale finalize folded in) ----------------
__global__ void scan1_kernel(int M) {
    __shared__ int s[1024];
    int tid = threadIdx.x;
    int i = blockIdx.x * 1024 + tid;
    int v = (i < M) ? g_cnt_in[i] : 0;
    if (i < M) {
        g_sout[i] = rsqrtf((float)max(g_cnt_out[i], 1));
        g_sin [i] = rsqrtf((float)max(v, 1));
    }
    s[tid] = v;
    __syncthreads();
    #pragma unroll
    for (int off = 1; off < 1024; off <<= 1) {
        int t = (tid >= off) ? s[tid - off] : 0;
        __syncthreads();
        s[tid] += t;
        __syncthreads();
    }
    if (i < M) g_rowstart[i] = s[tid] - v;
    if (tid == 1023) g_blocksum[blockIdx.x] = s[1023];
}

__global__ void scan2_kernel(int nb) {
    __shared__ int s[128];
    int tid = threadIdx.x;
    int v = (tid < nb) ? g_blocksum[tid] : 0;
    s[tid] = v;
    __syncthreads();
    #pragma unroll
    for (int off = 1; off < 128; off <<= 1) {
        int t = (tid >= off) ? s[tid - off] : 0;
        __syncthreads();
        s[tid] += t;
        __syncthreads();
    }
    if (tid < nb) g_blocksum[tid] = s[tid] - v;
}

// Phase 3: add block offsets; seed cursor with rowstart; sentinel.
__global__ void scan3_kernel(int M, int E) {
    int i = blockIdx.x * blockDim.x + threadIdx.x;
    if (i < M) {
        int v = g_rowstart[i] + g_blocksum[i >> 10];
        g_rowstart[i] = v;
        g_cursor[i] = v;
    }
    if (i == 0) g_rowstart[M] = E;
}

// ---------------- CSR fill ----------------
__global__ void fill_kernel(const int* __restrict__ src, const int* __restrict__ dst, int E) {
    int i = blockIdx.x * blockDim.x + threadIdx.x;
    int stride = gridDim.x * blockDim.x;
    for (; i < E; i += stride) {
        int pos = atomicAdd(&g_cursor[dst[i]], 1);
        g_esrc[pos] = src[i];
    }
}

// ---------------- tf32 helpers ----------------
__device__ __forceinline__ uint32_t f2tf32(float f) {
    uint32_t r;
    asm("cvt.rna.tf32.f32 %0, %1;" : "=r"(r) : "f"(f));
    return r;
}

__device__ __forceinline__ void mma_tf32(float* c, const uint32_t* a, const uint32_t* b) {
    asm volatile(
        "mma.sync.aligned.m16n8k8.row.col.f32.tf32.tf32.f32 "
        "{%0,%1,%2,%3}, {%4,%5,%6,%7}, {%8,%9}, {%0,%1,%2,%3};\n"
        : "+f"(c[0]), "+f"(c[1]), "+f"(c[2]), "+f"(c[3])
        : "r"(a[0]), "r"(a[1]), "r"(a[2]), "r"(a[3]), "r"(b[0]), "r"(b[1]));
}

// ---------------- tf32 GEMM body (device function; caller provides block coords) ----------------
// LAYER==1: g_XWh  = features @ W1 (UNscaled)   [A fp32, K=512, N=256]
// LAYER==2: g_H2ph = g_A2h @ W2                 [A fp16, K=256, N=128]
// BM=128, BN=128, BK=16; 8 warps 2(M)x4(N); warp tile 64x32 of m16n8k8 mmas.
template <int LAYER>
__device__ __forceinline__ void gemm_body(const float* __restrict__ A_ext,
                                          const float* __restrict__ B, int M,
                                          int bx, int by)
{
    const int K = (LAYER == 1) ? INDIM : H1DIM;
    const int N = (LAYER == 1) ? H1DIM : H2DIM;
    __half* C = (LAYER == 1) ? g_XWh : g_H2ph;

    const int BM = 128, BK = 16;
    const int AS = 136;
    __shared__ uint32_t As[2][BK * AS];
    __shared__ uint32_t Bs[2][BK * AS];

    int tid = threadIdx.x;
    int lane = tid & 31;
    int w = tid >> 5;
    int wm = w & 1;
    int wn = w >> 1;
    int g = lane >> 2, t4 = lane & 3;

    int row0 = by * BM;
    int col0 = bx * 128;

    int ar = tid >> 1, ac = (tid & 1) * 8;
    int arow = row0 + ar;
    bool rowok = (arow < M);

    int br = tid >> 4, bc = (tid & 15) * 8;

    float acc[4][4][4];
    #pragma unroll
    for (int mt = 0; mt < 4; mt++)
        #pragma unroll
        for (int nt = 0; nt < 4; nt++)
            #pragma unroll
            for (int i = 0; i < 4; i++) acc[mt][nt][i] = 0.f;

    float av[8];
    float4 b0v, b1v;

    auto load_regs = [&](int k0) {
        if (rowok) {
            if (LAYER == 1) {
                const float4* ap = reinterpret_cast<const float4*>(A_ext + (size_t)arow * K + k0 + ac);
                float4 a0 = ap[0], a1 = ap[1];
                av[0]=a0.x; av[1]=a0.y; av[2]=a0.z; av[3]=a0.w;
                av[4]=a1.x; av[5]=a1.y; av[6]=a1.z; av[7]=a1.w;
            } else {
                uint4 ah = *reinterpret_cast<const uint4*>(g_A2h + (size_t)arow * K + k0 + ac);
                float2 p0 = __half22float2(*reinterpret_cast<__half2*>(&ah.x));
                float2 p1 = __half22float2(*reinterpret_cast<__half2*>(&ah.y));
                float2 p2 = __half22float2(*reinterpret_cast<__half2*>(&ah.z));
                float2 p3 = __half22float2(*reinterpret_cast<__half2*>(&ah.w));
                av[0]=p0.x; av[1]=p0.y; av[2]=p1.x; av[3]=p1.y;
                av[4]=p2.x; av[5]=p2.y; av[6]=p3.x; av[7]=p3.y;
            }
        } else {
            #pragma unroll
            for (int i = 0; i < 8; i++) av[i] = 0.f;
        }
        const float4* bp = reinterpret_cast<const float4*>(B + (size_t)(k0 + br) * N + col0 + bc);
        b0v = bp[0]; b1v = bp[1];
    };

    auto store_smem = [&](int b) {
        #pragma unroll
        for (int i = 0; i < 8; i++)
            As[b][(ac + i) * AS + ar] = f2tf32(av[i]);
        Bs[b][br * AS + bc + 0] = f2tf32(b0v.x);
        Bs[b][br * AS + bc + 1] = f2tf32(b0v.y);
        Bs[b][br * AS + bc + 2] = f2tf32(b0v.z);
        Bs[b][br * AS + bc + 3] = f2tf32(b0v.w);
        Bs[b][br * AS + bc + 4] = f2tf32(b1v.x);
        Bs[b][br * AS + bc + 5] = f2tf32(b1v.y);
        Bs[b][br * AS + bc + 6] = f2tf32(b1v.z);
        Bs[b][br * AS + bc + 7] = f2tf32(b1v.w);
    };

    load_regs(0);
    store_smem(0);
    __syncthreads();

    int buf = 0;
    for (int k0 = 0; k0 < K; k0 += BK) {
        bool more = (k0 + BK < K);
        if (more) load_regs(k0 + BK);

        #pragma unroll
        for (int kk = 0; kk < BK; kk += 8) {
            uint32_t af[4][4], bf[4][2];
            #pragma unroll
            for (int mt = 0; mt < 4; mt++) {
                int m = wm * 64 + mt * 16 + g;
                af[mt][0] = As[buf][(kk + t4) * AS + m];
                af[mt][1] = As[buf][(kk + t4) * AS + m + 8];
                af[mt][2] = As[buf][(kk + t4 + 4) * AS + m];
                af[mt][3] = As[buf][(kk + t4 + 4) * AS + m + 8];
            }
            #pragma unroll
            for (int nt = 0; nt < 4; nt++) {
                int n = wn * 32 + nt * 8 + g;
                bf[nt][0] = Bs[buf][(kk + t4) * AS + n];
                bf[nt][1] = Bs[buf][(kk + t4 + 4) * AS + n];
            }
            #pragma unroll
            for (int mt = 0; mt < 4; mt++)
                #pragma unroll
                for (int nt = 0; nt < 4; nt++)
                    mma_tf32(acc[mt][nt], af[mt], bf[nt]);
        }

        if (more) store_smem(buf ^ 1);
        __syncthreads();
        buf ^= 1;
    }

    #pragma unroll
    for (int mt = 0; mt < 4; mt++) {
        int r = row0 + wm * 64 + mt * 16 + g;
        #pragma unroll
        for (int nt = 0; nt < 4; nt++) {
            int cb = col0 + wn * 32 + nt * 8 + t4 * 2;
            if (r < M) {
                __half2 v = __floats2half2_rn(acc[mt][nt][0], acc[mt][nt][1]);
                *reinterpret_cast<__half2*>(C + (size_t)r * N + cb) = v;
            }
            if (r + 8 < M) {
                __half2 v = __floats2half2_rn(acc[mt][nt][2], acc[mt][nt][3]);
                *reinterpret_cast<__half2*>(C + (size_t)(r + 8) * N + cb) = v;
            }
        }
    }
}

// ---------------- fused: degree count (odd blocks) + FULL GEMM1 (even blocks) ----------------
__global__ __launch_bounds__(256, 2)
void count_gemm1_kernel(const float* __restrict__ features, const float* __restrict__ W1,
                        const int* __restrict__ src, const int* __restrict__ dst,
                        int M, int E)
{
    int G = gridDim.x >> 1;
    if ((blockIdx.x & 1) == 0) {
        int id = blockIdx.x >> 1;            // 0 .. 2*nby-1
        gemm_body<1>(features, W1, M, id & 1, id >> 1);
    } else {
        int fid = blockIdx.x >> 1;
        int i = fid * 256 + threadIdx.x;
        int stride = G * 256;
        for (; i < E; i += stride) {
            atomicAdd(&g_cnt_out[src[i]], 1);
            atomicAdd(&g_cnt_in [dst[i]], 1);
        }
    }
}

// ---------------- GEMM2 ----------------
__global__ __launch_bounds__(256, 2)
void gemm2_kernel(const float* __restrict__ B, int M)
{
    gemm_body<2>(nullptr, B, M, blockIdx.x, blockIdx.y);
}

// ---------------- layer-1 aggregation: sum s_out[src]*XWu[src], + epilogue, fp16 out ----------------
// g_A2h[n,:] = relu( (sum_{e: dst==n} s_out[src_e]*XWu[src_e,:]) * s_in[n] + b1 ) * s_out[n]
__global__ __launch_bounds__(256)
void agg1_kernel(const float* __restrict__ b1, int M)
{
    int warp = (blockIdx.x * blockDim.x + threadIdx.x) >> 5;
    int lane = threadIdx.x & 31;
    int nw = (gridDim.x * blockDim.x) >> 5;
    float4 bb0 = *reinterpret_cast<const float4*>(b1 + lane * 8);
    float4 bb1 = *reinterpret_cast<const float4*>(b1 + lane * 8 + 4);

    for (int n = warp; n < M; n += nw) {
        int beg = g_rowstart[n], end = g_rowstart[n + 1];
        float a[8];
        #pragma unroll
        for (int i = 0; i < 8; i++) a[i] = 0.f;
        for (int e0 = beg; e0 < end; e0 += 32) {
            int mye = e0 + lane;
            int sv = 0; float scv = 0.f;
            if (mye < end) { sv = g_esrc[mye]; scv = g_sout[sv]; }
            int cnt = min(32, end - e0);
            for (int j = 0; j < cnt; j++) {
                int s = __shfl_sync(0xffffffff, sv, j);
                float sc = __shfl_sync(0xffffffff, scv, j);
                uint4 v = reinterpret_cast<const uint4*>(g_XWh + (size_t)s * H1DIM)[lane];
                float2 p0 = __half22float2(*reinterpret_cast<__half2*>(&v.x));
                float2 p1 = __half22float2(*reinterpret_cast<__half2*>(&v.y));
                float2 p2 = __half22float2(*reinterpret_cast<__half2*>(&v.z));
                float2 p3 = __half22float2(*reinterpret_cast<__half2*>(&v.w));
                a[0] = fmaf(p0.x, sc, a[0]); a[1] = fmaf(p0.y, sc, a[1]);
                a[2] = fmaf(p1.x, sc, a[2]); a[3] = fmaf(p1.y, sc, a[3]);
                a[4] = fmaf(p2.x, sc, a[4]); a[5] = fmaf(p2.y, sc, a[5]);
                a[6] = fmaf(p3.x, sc, a[6]); a[7] = fmaf(p3.y, sc, a[7]);
            }
        }
        float si = g_sin[n], so = g_sout[n];
        float o[8];
        o[0] = fmaxf(fmaf(a[0], si, bb0.x), 0.f) * so;
        o[1] = fmaxf(fmaf(a[1], si, bb0.y), 0.f) * so;
        o[2] = fmaxf(fmaf(a[2], si, bb0.z), 0.f) * so;
        o[3] = fmaxf(fmaf(a[3], si, bb0.w), 0.f) * so;
        o[4] = fmaxf(fmaf(a[4], si, bb1.x), 0.f) * so;
        o[5] = fmaxf(fmaf(a[5], si, bb1.y), 0.f) * so;
        o[6] = fmaxf(fmaf(a[6], si, bb1.z), 0.f) * so;
        o[7] = fmaxf(fmaf(a[7], si, bb1.w), 0.f) * so;
        uint4 pack;
        *reinterpret_cast<__half2*>(&pack.x) = __floats2half2_rn(o[0], o[1]);
        *reinterpret_cast<__half2*>(&pack.y) = __floats2half2_rn(o[2], o[3]);
        *reinterpret_cast<__half2*>(&pack.z) = __floats2half2_rn(o[4], o[5]);
        *reinterpret_cast<__half2*>(&pack.w) = __floats2half2_rn(o[6], o[7]);
        reinterpret_cast<uint4*>(g_A2h + (size_t)n * H1DIM)[lane] = pack;
    }
}

// ---------------- layer-2 aggregation (fp16 gather) + full MLP head ----------------
__global__ __launch_bounds__(256)
void agg2_head_kernel(const float* __restrict__ b2,
                      const float* __restrict__ Wo1, const float* __restrict__ bo1,
                      const float* __restrict__ Wo2, const float* __restrict__ bo2,
                      float* __restrict__ out, int M)
{
    __shared__ float sW1[H2DIM * ENDDIM];   // 32 KB
    __shared__ float sW2[ENDDIM];
    __shared__ float sb1[ENDDIM];
    __shared__ float h2[8][H2DIM];

    int tid = threadIdx.x;
    for (int i = tid; i < H2DIM * ENDDIM; i += blockDim.x) sW1[i] = Wo1[i];
    if (tid < ENDDIM) { sW2[tid] = Wo2[tid]; sb1[tid] = bo1[tid]; }
    __syncthreads();

    int warp = tid >> 5, lane = tid & 31;
    int gw = blockIdx.x * 8 + warp;
    int nw = gridDim.x * 8;
    float bo2v = bo2[0];
    float4 bb = reinterpret_cast<const float4*>(b2)[lane];

    for (int n = gw; n < M; n += nw) {
        int beg = g_rowstart[n], end = g_rowstart[n + 1];
        float a0 = 0.f, a1 = 0.f, a2 = 0.f, a3 = 0.f;
        for (int e0 = beg; e0 < end; e0 += 32) {
            int mye = e0 + lane;
            int sv = (mye < end) ? g_esrc[mye] : 0;
            int cnt = min(32, end - e0);
            for (int j = 0; j < cnt; j++) {
                int s = __shfl_sync(0xffffffff, sv, j);
                uint2 v = reinterpret_cast<const uint2*>(g_H2ph + (size_t)s * H2DIM)[lane];
                float2 p0 = __half22float2(*reinterpret_cast<__half2*>(&v.x));
                float2 p1 = __half22float2(*reinterpret_cast<__half2*>(&v.y));
                a0 += p0.x; a1 += p0.y; a2 += p1.x; a3 += p1.y;
            }
        }
        float si = g_sin[n];
        h2[warp][lane * 4 + 0] = fmaf(a0, si, bb.x);
        h2[warp][lane * 4 + 1] = fmaf(a1, si, bb.y);
        h2[warp][lane * 4 + 2] = fmaf(a2, si, bb.z);
        h2[warp][lane * 4 + 3] = fmaf(a3, si, bb.w);
        __syncwarp();

        float accs = 0.f;
        #pragma unroll
        for (int jj = 0; jj < 2; jj++) {
            int j = lane + jj * 32;
            float t = sb1[j];
            #pragma unroll 8
            for (int k = 0; k < H2DIM; k++)
                t = fmaf(h2[warp][k], sW1[k * ENDDIM + j], t);
            t = fmaxf(t, 0.f);
            accs = fmaf(t, sW2[j], accs);
        }
        #pragma unroll
        for (int o = 16; o > 0; o >>= 1)
            accs += __shfl_down_sync(0xffffffff, accs, o);
        if (lane == 0) out[n] = accs + bo2v;
        __syncwarp();
    }
}

// ---------------- launch ----------------
extern "C" void kernel_launch(void* const* d_in, const int* in_sizes, int n_in,
                              void* d_out, int out_size)
{
    const float* features = (const float*)d_in[0];
    const int*   src      = (const int*)  d_in[1];
    const int*   dst      = (const int*)  d_in[2];
    const float* W1       = (const float*)d_in[3];
    const float* b1       = (const float*)d_in[4];
    const float* W2       = (const float*)d_in[5];
    const float* b2       = (const float*)d_in[6];
    const float* Wo1      = (const float*)d_in[7];
    const float* bo1      = (const float*)d_in[8];
    const float* Wo2      = (const float*)d_in[9];
    const float* bo2      = (const float*)d_in[10];
    float* out = (float*)d_out;

    int M = in_sizes[0] / INDIM;   // 100000
    int E = in_sizes[1];           // 3200000

    zero_kernel<<<(M + 255) / 256, 256>>>(M);

    // Fused: degree count (odd blocks) + FULL unscaled GEMM1 (even blocks).
    int gemmBlocks = 2 * ((M + 127) / 128);            // 1564
    count_gemm1_kernel<<<2 * gemmBlocks, 256>>>(features, W1, src, dst, M, E);

    int nb = (M + 1023) / 1024;    // 98
    scan1_kernel<<<nb, 1024>>>(M);         // also computes s_out/s_in
    scan2_kernel<<<1, 128>>>(nb);
    scan3_kernel<<<(M + 255) / 256, 256>>>(M, E);

    fill_kernel<<<2048, 256>>>(src, dst, E);

    agg1_kernel<<<(M * 32 + 255) / 256, 256>>>(b1, M);

    // Layer 2: g_H2ph = g_A2h @ W2   (M x 256 @ 256 x 128)
    gemm2_kernel<<<dim3(H2DIM / 128, (M + 127) / 128), 256>>>(W2, M);
    agg2_head_kernel<<<(M + 7) / 8, 256>>>(b2, Wo1, bo1, Wo2, bo2, out, M);
}

// round 16
// speedup vs baseline: 1.2081x; 1.1874x over previous
#include <cuda_runtime.h>
#include <cuda_fp16.h>
#include <cstdint>

#define NODES  100000
#define INDIM  512
#define H1DIM  256
#define H2DIM  128
#define ENDDIM 64
#define MAXE   3200000

// ---------------- scratch (device globals; referenced ONLY from device code) ----------------
__device__ __align__(128) __half g_XWh [(size_t)NODES * H1DIM];  // (X*s_out)@W1, fp16
__device__ __align__(128) __half g_A2h [(size_t)NODES * H1DIM];  // relu(agg1*s_in+b1)*s_out, fp16
__device__ __align__(128) __half g_H2ph[(size_t)NODES * H2DIM];  // A2@W2, fp16
__device__ __align__(128) float  g_sout[NODES];
__device__ __align__(128) float  g_sin [NODES];
__device__ __align__(16)  int    g_cnt_in [NODES];
__device__ __align__(16)  int    g_cnt_out[NODES];
__device__ __align__(16)  int    g_cursor [NODES];
__device__ __align__(16)  int    g_rowstart[NODES + 1];
__device__ __align__(16)  int    g_esrc[MAXE];
__device__ __align__(16)  int    g_blocksum[128];

// ---------------- zero count arrays ----------------
__global__ void zero_kernel(int M) {
    int i = blockIdx.x * blockDim.x + threadIdx.x;
    if (i < M) { g_cnt_in[i] = 0; g_cnt_out[i] = 0; }
}

// ---------------- degree counts (int atomics) ----------------
__global__ void count_kernel(const int* __restrict__ src, const int* __restrict__ dst, int E) {
    int i = blockIdx.x * blockDim.x + threadIdx.x;
    int stride = gridDim.x * blockDim.x;
    for (; i < E; i += stride) {
        atomicAdd(&g_cnt_out[src[i]], 1);
        atomicAdd(&g_cnt_in [dst[i]], 1);
    }
}

// ---------------- scan phase 1 (+ degree->scale finalize folded in) ----------------
__global__ void scan1_kernel(int M) {
    __shared__ int s[1024];
    int tid = threadIdx.x;
    int i = blockIdx.x * 1024 + tid;
    int v = (i < M) ? g_cnt_in[i] : 0;
    if (i < M) {
        g_sout[i] = rsqrtf((float)max(g_cnt_out[i], 1));
        g_sin [i] = rsqrtf((float)max(v, 1));
    }
    s[tid] = v;
    __syncthreads();
    #pragma unroll
    for (int off = 1; off < 1024; off <<= 1) {
        int t = (tid >= off) ? s[tid - off] : 0;
        __syncthreads();
        s[tid] += t;
        __syncthreads();
    }
    if (i < M) g_rowstart[i] = s[tid] - v;
    if (tid == 1023) g_blocksum[blockIdx.x] = s[1023];
}

__global__ void scan2_kernel(int nb) {
    __shared__ int s[128];
    int tid = threadIdx.x;
    int v = (tid < nb) ? g_blocksum[tid] : 0;
    s[tid] = v;
    __syncthreads();
    #pragma unroll
    for (int off = 1; off < 128; off <<= 1) {
        int t = (tid >= off) ? s[tid - off] : 0;
        __syncthreads();
        s[tid] += t;
        __syncthreads();
    }
    if (tid < nb) g_blocksum[tid] = s[tid] - v;
}

// Phase 3: add block offsets; seed cursor with rowstart; sentinel.
__global__ void scan3_kernel(int M, int E) {
    int i = blockIdx.x * blockDim.x + threadIdx.x;
    if (i < M) {
        int v = g_rowstart[i] + g_blocksum[i >> 10];
        g_rowstart[i] = v;
        g_cursor[i] = v;
    }
    if (i == 0) g_rowstart[M] = E;
}

// ---------------- fp16 mma helper ----------------
__device__ __forceinline__ void mma_f16(float* c, const uint32_t* a, const uint32_t* b) {
    asm volatile(
        "mma.sync.aligned.m16n8k16.row.col.f32.f16.f16.f32 "
        "{%0,%1,%2,%3}, {%4,%5,%6,%7}, {%8,%9}, {%0,%1,%2,%3};\n"
        : "+f"(c[0]), "+f"(c[1]), "+f"(c[2]), "+f"(c[3])
        : "r"(a[0]), "r"(a[1]), "r"(a[2]), "r"(a[3]), "r"(b[0]), "r"(b[1]));
}

__device__ __forceinline__ uint32_t packh2(float lo, float hi) {
    __half2 h = __floats2half2_rn(lo, hi);
    return *reinterpret_cast<uint32_t*>(&h);
}

// ---------------- fp16 tensor-core GEMM body ----------------
// LAYER==1: g_XWh  = (features .* g_sout) @ W1   [A fp32, K=512, N=256]
// LAYER==2: g_H2ph = g_A2h @ W2                  [A fp16, K=256, N=128]
// BM=128, BN=128, BK=16 (k-elements; 8 packed uint32 rows); 8 warps 2(M)x4(N);
// warp tile 64x32; per K-tile: 16 m16n8k16 mmas. smem [k2][m]/[k2][n], half2 packed along k.
template <int LAYER>
__device__ __forceinline__ void gemm_body(const float* __restrict__ A_ext,
                                          const float* __restrict__ B, int M,
                                          int bx, int by)
{
    const int K = (LAYER == 1) ? INDIM : H1DIM;
    const int N = (LAYER == 1) ? H1DIM : H2DIM;
    __half* C = (LAYER == 1) ? g_XWh : g_H2ph;

    const int BM = 128, BK = 16;
    const int AS = 136;                       // uint32 stride, 8 mod 32 -> conflict-free frags
    __shared__ uint32_t As[2][8 * AS];        // As[b][k2][m]
    __shared__ uint32_t Bs[2][8 * AS];        // Bs[b][k2][n]

    int tid = threadIdx.x;
    int lane = tid & 31;
    int w = tid >> 5;
    int wm = w & 1;
    int wn = w >> 1;
    int g = lane >> 2, t4 = lane & 3;

    int row0 = by * BM;
    int col0 = bx * 128;

    // A loader: 2 threads/row, 8 consecutive k-elements each
    int ar = tid >> 1, ac = (tid & 1) * 8, ac2 = (tid & 1) * 4;
    int arow = row0 + ar;
    bool rowok = (arow < M);
    float sc = (LAYER == 1 && rowok) ? g_sout[arow] : 1.0f;

    // B loader: warp kp handles k-rows {2kp, 2kp+1}; lane covers 4 n-values
    int kp = tid >> 5, n4 = (tid & 31) * 4;

    float acc[4][4][4];
    #pragma unroll
    for (int mt = 0; mt < 4; mt++)
        #pragma unroll
        for (int nt = 0; nt < 4; nt++)
            #pragma unroll
            for (int i = 0; i < 4; i++) acc[mt][nt][i] = 0.f;

    float av[8];
    uint4 ahv;
    float4 b0v, b1v;

    auto load_regs = [&](int k0) {
        if (rowok) {
            if (LAYER == 1) {
                const float4* ap = reinterpret_cast<const float4*>(A_ext + (size_t)arow * K + k0 + ac);
                float4 a0 = ap[0], a1 = ap[1];
                av[0]=a0.x; av[1]=a0.y; av[2]=a0.z; av[3]=a0.w;
                av[4]=a1.x; av[5]=a1.y; av[6]=a1.z; av[7]=a1.w;
            } else {
                ahv = *reinterpret_cast<const uint4*>(g_A2h + (size_t)arow * K + k0 + ac);
            }
        } else {
            if (LAYER == 1) {
                #pragma unroll
                for (int i = 0; i < 8; i++) av[i] = 0.f;
            } else ahv = make_uint4(0, 0, 0, 0);
        }
        const float* bp = B + (size_t)(k0 + 2 * kp) * N + col0 + n4;
        b0v = *reinterpret_cast<const float4*>(bp);
        b1v = *reinterpret_cast<const float4*>(bp + N);
    };

    auto store_smem = [&](int b) {
        if (LAYER == 1) {
            As[b][(ac2 + 0) * AS + ar] = packh2(av[0] * sc, av[1] * sc);
            As[b][(ac2 + 1) * AS + ar] = packh2(av[2] * sc, av[3] * sc);
            As[b][(ac2 + 2) * AS + ar] = packh2(av[4] * sc, av[5] * sc);
            As[b][(ac2 + 3) * AS + ar] = packh2(av[6] * sc, av[7] * sc);
        } else {
            As[b][(ac2 + 0) * AS + ar] = ahv.x;
            As[b][(ac2 + 1) * AS + ar] = ahv.y;
            As[b][(ac2 + 2) * AS + ar] = ahv.z;
            As[b][(ac2 + 3) * AS + ar] = ahv.w;
        }
        uint4 bw;
        bw.x = packh2(b0v.x, b1v.x);
        bw.y = packh2(b0v.y, b1v.y);
        bw.z = packh2(b0v.z, b1v.z);
        bw.w = packh2(b0v.w, b1v.w);
        *reinterpret_cast<uint4*>(&Bs[b][kp * AS + n4]) = bw;
    };

    load_regs(0);
    store_smem(0);
    __syncthreads();

    int buf = 0;
    for (int k0 = 0; k0 < K; k0 += BK) {
        bool more = (k0 + BK < K);
        if (more) load_regs(k0 + BK);

        uint32_t af[4][4], bf[4][2];
        #pragma unroll
        for (int mt = 0; mt < 4; mt++) {
            int m = wm * 64 + mt * 16 + g;
            af[mt][0] = As[buf][t4 * AS + m];
            af[mt][1] = As[buf][t4 * AS + m + 8];
            af[mt][2] = As[buf][(t4 + 4) * AS + m];
            af[mt][3] = As[buf][(t4 + 4) * AS + m + 8];
        }
        #pragma unroll
        for (int nt = 0; nt < 4; nt++) {
            int n = wn * 32 + nt * 8 + g;
            bf[nt][0] = Bs[buf][t4 * AS + n];
            bf[nt][1] = Bs[buf][(t4 + 4) * AS + n];
        }
        #pragma unroll
        for (int mt = 0; mt < 4; mt++)
            #pragma unroll
            for (int nt = 0; nt < 4; nt++)
                mma_f16(acc[mt][nt], af[mt], bf[nt]);

        if (more) store_smem(buf ^ 1);
        __syncthreads();
        buf ^= 1;
    }

    #pragma unroll
    for (int mt = 0; mt < 4; mt++) {
        int r = row0 + wm * 64 + mt * 16 + g;
        #pragma unroll
        for (int nt = 0; nt < 4; nt++) {
            int cb = col0 + wn * 32 + nt * 8 + t4 * 2;
            if (r < M) {
                __half2 v = __floats2half2_rn(acc[mt][nt][0], acc[mt][nt][1]);
                *reinterpret_cast<__half2*>(C + (size_t)r * N + cb) = v;
            }
            if (r + 8 < M) {
                __half2 v = __floats2half2_rn(acc[mt][nt][2], acc[mt][nt][3]);
                *reinterpret_cast<__half2*>(C + (size_t)(r + 8) * N + cb) = v;
            }
        }
    }
}

// ---------------- fused: CSR fill (odd blocks) + FULL scaled GEMM1 (even blocks) ----------------
__global__ __launch_bounds__(256, 2)
void fill_gemm1_kernel(const float* __restrict__ features, const float* __restrict__ W1,
                       const int* __restrict__ src, const int* __restrict__ dst,
                       int M, int E)
{
    int G = gridDim.x >> 1;
    if ((blockIdx.x & 1) == 0) {
        int id = blockIdx.x >> 1;
        gemm_body<1>(features, W1, M, id & 1, id >> 1);
    } else {
        int fid = blockIdx.x >> 1;
        int i = fid * 256 + threadIdx.x;
        int stride = G * 256;
        for (; i < E; i += stride) {
            int pos = atomicAdd(&g_cursor[dst[i]], 1);
            g_esrc[pos] = src[i];
        }
    }
}

// ---------------- GEMM2 ----------------
__global__ __launch_bounds__(256, 2)
void gemm2_kernel(const float* __restrict__ B, int M)
{
    gemm_body<2>(nullptr, B, M, blockIdx.x, blockIdx.y);
}

// ---------------- layer-1 aggregation (fp16 gather, 4-way MLP) + epilogue, fp16 out ----------------
// g_A2h[n,:] = relu( (sum_{e: dst==n} XWh[src_e,:]) * s_in[n] + b1 ) * s_out[n]
__global__ __launch_bounds__(256)
void agg1_kernel(const float* __restrict__ b1, int M)
{
    int warp = (blockIdx.x * blockDim.x + threadIdx.x) >> 5;
    int lane = threadIdx.x & 31;
    int nw = (gridDim.x * blockDim.x) >> 5;
    float4 bb0 = *reinterpret_cast<const float4*>(b1 + lane * 8);
    float4 bb1 = *reinterpret_cast<const float4*>(b1 + lane * 8 + 4);

    for (int n = warp; n < M; n += nw) {
        int beg = g_rowstart[n], end = g_rowstart[n + 1];
        float a[8];
        #pragma unroll
        for (int i = 0; i < 8; i++) a[i] = 0.f;
        for (int e0 = beg; e0 < end; e0 += 32) {
            int mye = e0 + lane;
            int sv = (mye < end) ? g_esrc[mye] : 0;
            int cnt = min(32, end - e0);
            int j = 0;
            for (; j + 4 <= cnt; j += 4) {
                int s0 = __shfl_sync(0xffffffff, sv, j);
                int s1 = __shfl_sync(0xffffffff, sv, j + 1);
                int s2 = __shfl_sync(0xffffffff, sv, j + 2);
                int s3 = __shfl_sync(0xffffffff, sv, j + 3);
                uint4 v0 = reinterpret_cast<const uint4*>(g_XWh + (size_t)s0 * H1DIM)[lane];
                uint4 v1 = reinterpret_cast<const uint4*>(g_XWh + (size_t)s1 * H1DIM)[lane];
                uint4 v2 = reinterpret_cast<const uint4*>(g_XWh + (size_t)s2 * H1DIM)[lane];
                uint4 v3 = reinterpret_cast<const uint4*>(g_XWh + (size_t)s3 * H1DIM)[lane];
                #pragma unroll
                for (int q = 0; q < 4; q++) {
                    uint4 v = (q == 0) ? v0 : (q == 1) ? v1 : (q == 2) ? v2 : v3;
                    float2 p0 = __half22float2(*reinterpret_cast<__half2*>(&v.x));
                    float2 p1 = __half22float2(*reinterpret_cast<__half2*>(&v.y));
                    float2 p2 = __half22float2(*reinterpret_cast<__half2*>(&v.z));
                    float2 p3 = __half22float2(*reinterpret_cast<__half2*>(&v.w));
                    a[0] += p0.x; a[1] += p0.y; a[2] += p1.x; a[3] += p1.y;
                    a[4] += p2.x; a[5] += p2.y; a[6] += p3.x; a[7] += p3.y;
                }
            }
            for (; j < cnt; j++) {
                int s = __shfl_sync(0xffffffff, sv, j);
                uint4 v = reinterpret_cast<const uint4*>(g_XWh + (size_t)s * H1DIM)[lane];
                float2 p0 = __half22float2(*reinterpret_cast<__half2*>(&v.x));
                float2 p1 = __half22float2(*reinterpret_cast<__half2*>(&v.y));
                float2 p2 = __half22float2(*reinterpret_cast<__half2*>(&v.z));
                float2 p3 = __half22float2(*reinterpret_cast<__half2*>(&v.w));
                a[0] += p0.x; a[1] += p0.y; a[2] += p1.x; a[3] += p1.y;
                a[4] += p2.x; a[5] += p2.y; a[6] += p3.x; a[7] += p3.y;
            }
        }
        float si = g_sin[n], so = g_sout[n];
        float o[8];
        o[0] = fmaxf(fmaf(a[0], si, bb0.x), 0.f) * so;
        o[1] = fmaxf(fmaf(a[1], si, bb0.y), 0.f) * so;
        o[2] = fmaxf(fmaf(a[2], si, bb0.z), 0.f) * so;
        o[3] = fmaxf(fmaf(a[3], si, bb0.w), 0.f) * so;
        o[4] = fmaxf(fmaf(a[4], si, bb1.x), 0.f) * so;
        o[5] = fmaxf(fmaf(a[5], si, bb1.y), 0.f) * so;
        o[6] = fmaxf(fmaf(a[6], si, bb1.z), 0.f) * so;
        o[7] = fmaxf(fmaf(a[7], si, bb1.w), 0.f) * so;
        uint4 pack;
        *reinterpret_cast<__half2*>(&pack.x) = __floats2half2_rn(o[0], o[1]);
        *reinterpret_cast<__half2*>(&pack.y) = __floats2half2_rn(o[2], o[3]);
        *reinterpret_cast<__half2*>(&pack.z) = __floats2half2_rn(o[4], o[5]);
        *reinterpret_cast<__half2*>(&pack.w) = __floats2half2_rn(o[6], o[7]);
        reinterpret_cast<uint4*>(g_A2h + (size_t)n * H1DIM)[lane] = pack;
    }
}

// ---------------- layer-2 aggregation (fp16 gather, 4-way MLP) + full MLP head ----------------
__global__ __launch_bounds__(256)
void agg2_head_kernel(const float* __restrict__ b2,
                      const float* __restrict__ Wo1, const float* __restrict__ bo1,
                      const float* __restrict__ Wo2, const float* __restrict__ bo2,
                      float* __restrict__ out, int M)
{
    __shared__ float sW1[H2DIM * ENDDIM];   // 32 KB
    __shared__ float sW2[ENDDIM];
    __shared__ float sb1[ENDDIM];
    __shared__ float h2[8][H2DIM];

    int tid = threadIdx.x;
    for (int i = tid; i < H2DIM * ENDDIM; i += blockDim.x) sW1[i] = Wo1[i];
    if (tid < ENDDIM) { sW2[tid] = Wo2[tid]; sb1[tid] = bo1[tid]; }
    __syncthreads();

    int warp = tid >> 5, lane = tid & 31;
    int gw = blockIdx.x * 8 + warp;
    int nw = gridDim.x * 8;
    float bo2v = bo2[0];
    float4 bb = reinterpret_cast<const float4*>(b2)[lane];

    for (int n = gw; n < M; n += nw) {
        int beg = g_rowstart[n], end = g_rowstart[n + 1];
        float a0 = 0.f, a1 = 0.f, a2 = 0.f, a3 = 0.f;
        for (int e0 = beg; e0 < end; e0 += 32) {
            int mye = e0 + lane;
            int sv = (mye < end) ? g_esrc[mye] : 0;
            int cnt = min(32, end - e0);
            int j = 0;
            for (; j + 4 <= cnt; j += 4) {
                int s0 = __shfl_sync(0xffffffff, sv, j);
                int s1 = __shfl_sync(0xffffffff, sv, j + 1);
                int s2 = __shfl_sync(0xffffffff, sv, j + 2);
                int s3 = __shfl_sync(0xffffffff, sv, j + 3);
                uint2 v0 = reinterpret_cast<const uint2*>(g_H2ph + (size_t)s0 * H2DIM)[lane];
                uint2 v1 = reinterpret_cast<const uint2*>(g_H2ph + (size_t)s1 * H2DIM)[lane];
                uint2 v2 = reinterpret_cast<const uint2*>(g_H2ph + (size_t)s2 * H2DIM)[lane];
                uint2 v3 = reinterpret_cast<const uint2*>(g_H2ph + (size_t)s3 * H2DIM)[lane];
                #pragma unroll
                for (int q = 0; q < 4; q++) {
                    uint2 v = (q == 0) ? v0 : (q == 1) ? v1 : (q == 2) ? v2 : v3;
                    float2 p0 = __half22float2(*reinterpret_cast<__half2*>(&v.x));
                    float2 p1 = __half22float2(*reinterpret_cast<__half2*>(&v.y));
                    a0 += p0.x; a1 += p0.y; a2 += p1.x; a3 += p1.y;
                }
            }
            for (; j < cnt; j++) {
                int s = __shfl_sync(0xffffffff, sv, j);
                uint2 v = reinterpret_cast<const uint2*>(g_H2ph + (size_t)s * H2DIM)[lane];
                float2 p0 = __half22float2(*reinterpret_cast<__half2*>(&v.x));
                float2 p1 = __half22float2(*reinterpret_cast<__half2*>(&v.y));
                a0 += p0.x; a1 += p0.y; a2 += p1.x; a3 += p1.y;
            }
        }
        float si = g_sin[n];
        h2[warp][lane * 4 + 0] = fmaf(a0, si, bb.x);
        h2[warp][lane * 4 + 1] = fmaf(a1, si, bb.y);
        h2[warp][lane * 4 + 2] = fmaf(a2, si, bb.z);
        h2[warp][lane * 4 + 3] = fmaf(a3, si, bb.w);
        __syncwarp();

        float accs = 0.f;
        #pragma unroll
        for (int jj = 0; jj < 2; jj++) {
            int j = lane + jj * 32;
            float t = sb1[j];
            #pragma unroll 8
            for (int k = 0; k < H2DIM; k++)
                t = fmaf(h2[warp][k], sW1[k * ENDDIM + j], t);
            t = fmaxf(t, 0.f);
            accs = fmaf(t, sW2[j], accs);
        }
        #pragma unroll
        for (int o = 16; o > 0; o >>= 1)
            accs += __shfl_down_sync(0xffffffff, accs, o);
        if (lane == 0) out[n] = accs + bo2v;
        __syncwarp();
    }
}

// ---------------- launch ----------------
extern "C" void kernel_launch(void* const* d_in, const int* in_sizes, int n_in,
                              void* d_out, int out_size)
{
    const float* features = (const float*)d_in[0];
    const int*   src      = (const int*)  d_in[1];
    const int*   dst      = (const int*)  d_in[2];
    const float* W1       = (const float*)d_in[3];
    const float* b1       = (const float*)d_in[4];
    const float* W2       = (const float*)d_in[5];
    const float* b2       = (const float*)d_in[6];
    const float* Wo1      = (const float*)d_in[7];
    const float* bo1      = (const float*)d_in[8];
    const float* Wo2      = (const float*)d_in[9];
    const float* bo2      = (const float*)d_in[10];
    float* out = (float*)d_out;

    int M = in_sizes[0] / INDIM;   // 100000
    int E = in_sizes[1];           // 3200000

    zero_kernel<<<(M + 255) / 256, 256>>>(M);
    count_kernel<<<2048, 256>>>(src, dst, E);

    int nb = (M + 1023) / 1024;    // 98
    scan1_kernel<<<nb, 1024>>>(M);         // also computes s_out/s_in
    scan2_kernel<<<1, 128>>>(nb);
    scan3_kernel<<<(M + 255) / 256, 256>>>(M, E);

    // Fused: CSR fill (odd blocks) + scaled GEMM1 (even blocks).
    int gemmBlocks = 2 * ((M + 127) / 128);            // 1564
    fill_gemm1_kernel<<<2 * gemmBlocks, 256>>>(features, W1, src, dst, M, E);

    agg1_kernel<<<(M * 32 + 255) / 256, 256>>>(b1, M);

    // Layer 2: g_H2ph = g_A2h @ W2   (M x 256 @ 256 x 128)
    gemm2_kernel<<<dim3(H2DIM / 128, (M + 127) / 128), 256>>>(W2, M);
    agg2_head_kernel<<<(M + 7) / 8, 256>>>(b2, Wo1, bo1, Wo2, bo2, out, M);
}